// round 15
// baseline (speedup 1.0000x reference)
#include <cuda_runtime.h>
#include <cuda_bf16.h>
#include <cuda_fp16.h>
#include <math.h>
#include <stdint.h>

#define Bb 2
#define Tt 2048
#define Dd 1024
#define Hh 16
#define Ll 8
#define II 4096
#define HD 64
#define MASK_BIAS -10000.0f
#define LN_EPS 1e-5f
#define KVSCALE 64.0f
#define KVISCALE 0.015625f

// ================= scratch =================
__device__ float g_h[Bb * Tt * Dd];
__device__ __half g_qkvhi[Bb * Tt * 3 * Dd], g_qkvlo[Bb * Tt * 3 * Dd];
__device__ __half g_x16[Bb * Tt * Dd];
__device__ __half g_ctx16[Bb * Tt * Dd];
__device__ __half g_ff16[Bb * Tt * II];
// transposed fp16 weight slabs [L][N][K]
__device__ __half g_wqkv[Ll * 3 * Dd * Dd];
__device__ __half g_wproj[Ll * Dd * Dd];
__device__ __half g_wfc[Ll * II * Dd];
__device__ __half g_wfcp[Ll * Dd * II];

__device__ __forceinline__ uint32_t smem_u32(const void* p) {
    uint32_t a;
    asm("{ .reg .u64 t; cvta.to.shared.u64 t, %1; cvt.u32.u64 %0, t; }" : "=r"(a) : "l"(p));
    return a;
}
__device__ __forceinline__ void ldsm4(uint32_t* r, uint32_t addr) {
    asm volatile("ldmatrix.sync.aligned.m8n8.x4.shared.b16 {%0,%1,%2,%3}, [%4];"
                 : "=r"(r[0]), "=r"(r[1]), "=r"(r[2]), "=r"(r[3]) : "r"(addr));
}
__device__ __forceinline__ void ldsm4t(uint32_t* r, uint32_t addr) {
    asm volatile("ldmatrix.sync.aligned.m8n8.x4.trans.shared.b16 {%0,%1,%2,%3}, [%4];"
                 : "=r"(r[0]), "=r"(r[1]), "=r"(r[2]), "=r"(r[3]) : "r"(addr));
}
__device__ __forceinline__ void mma_f16(float* d, const uint32_t* a, uint32_t b0, uint32_t b1) {
    asm volatile("mma.sync.aligned.m16n8k16.row.col.f32.f16.f16.f32 "
                 "{%0,%1,%2,%3}, {%4,%5,%6,%7}, {%8,%9}, {%0,%1,%2,%3};"
                 : "+f"(d[0]), "+f"(d[1]), "+f"(d[2]), "+f"(d[3])
                 : "r"(a[0]), "r"(a[1]), "r"(a[2]), "r"(a[3]), "r"(b0), "r"(b1));
}
__device__ __forceinline__ uint32_t packh(float x, float y) {
    __half2 t = __floats2half2_rn(x, y);
    return *reinterpret_cast<uint32_t*>(&t);
}
__device__ __forceinline__ void cpa16(uint32_t s, const void* g) {
    asm volatile("cp.async.cg.shared.global [%0], [%1], 16;" :: "r"(s), "l"(g));
}

// ================= small kernels =================
__global__ void copy_kernel(const float* __restrict__ src) {
    int i = blockIdx.x * blockDim.x + threadIdx.x;
    reinterpret_cast<float4*>(g_h)[i] = reinterpret_cast<const float4*>(src)[i];
}

// weight transpose + fp16 convert: W[K][N] -> W'[N][K], 64x64 tiles, vectorized
__global__ void wconv_kernel(const float* __restrict__ W, __half* __restrict__ Wo,
                             int K, int N) {
    __shared__ float s[64][65];
    int n0 = blockIdx.x * 64, k0 = blockIdx.y * 64;
    int tid = threadIdx.x;
    int lr = tid >> 4;          // 0..15
    int lc = (tid & 15) * 4;    // 0..60
#pragma unroll
    for (int i = 0; i < 4; i++) {
        int k = lr + i * 16;
        float4 v = *(const float4*)&W[(size_t)(k0 + k) * N + n0 + lc];
        s[k][lc] = v.x; s[k][lc + 1] = v.y; s[k][lc + 2] = v.z; s[k][lc + 3] = v.w;
    }
    __syncthreads();
    int n = tid >> 2;           // 0..63
    int ks = (tid & 3) * 16;    // 0,16,32,48
    union { __half h[16]; uint4 u[2]; } o;
#pragma unroll
    for (int j = 0; j < 16; j++) o.h[j] = __float2half(s[ks + j][n]);
    uint4* dst = (uint4*)&Wo[(size_t)(n0 + n) * K + k0 + ks];
    dst[0] = o.u[0];
    dst[1] = o.u[1];
}

template <bool F16OUT>
__global__ void ln_kernel(const float* __restrict__ x, const float* __restrict__ w,
                          const float* __restrict__ b, float* __restrict__ out,
                          __half* __restrict__ o16) {
    int row = blockIdx.x;
    int tid = threadIdx.x;
    const float* xr = x + (size_t)row * Dd;
    float4 v = *(const float4*)&xr[tid * 4];
    float sum = v.x + v.y + v.z + v.w;
    float sq = v.x * v.x + v.y * v.y + v.z * v.z + v.w * v.w;
#pragma unroll
    for (int o = 16; o > 0; o >>= 1) {
        sum += __shfl_xor_sync(0xffffffffu, sum, o);
        sq += __shfl_xor_sync(0xffffffffu, sq, o);
    }
    __shared__ float ssum[8], ssq[8], stat[2];
    if ((tid & 31) == 0) { ssum[tid >> 5] = sum; ssq[tid >> 5] = sq; }
    __syncthreads();
    if (tid == 0) {
        float S = 0.f, Q = 0.f;
#pragma unroll
        for (int i = 0; i < 8; i++) { S += ssum[i]; Q += ssq[i]; }
        float mean = S * (1.0f / Dd);
        float var = Q * (1.0f / Dd) - mean * mean;
        stat[0] = mean;
        stat[1] = rsqrtf(var + LN_EPS);
    }
    __syncthreads();
    float mean = stat[0], rstd = stat[1];
    int c = tid * 4;
    float4 wv = *(const float4*)&w[c];
    float4 bv = *(const float4*)&b[c];
    float y0 = (v.x - mean) * rstd * wv.x + bv.x;
    float y1 = (v.y - mean) * rstd * wv.y + bv.y;
    float y2 = (v.z - mean) * rstd * wv.z + bv.z;
    float y3 = (v.w - mean) * rstd * wv.w + bv.w;
    if (F16OUT) {
        uint2 o;
        o.x = packh(y0, y1);
        o.y = packh(y2, y3);
        *(uint2*)&o16[(size_t)row * Dd + c] = o;
    } else {
        *(float4*)&out[(size_t)row * Dd + c] = make_float4(y0, y1, y2, y3);
    }
}

// ================= HMMA GEMM (fp16, 64x64 warp tile, 128 thr, 4-stage, 2 CTAs/SM) =================
// OUT: 0 = fp32 C, 1 = fp16 Cf, 2 = fp16 hi/lo qkv (K/V cols x64-scaled)
#define PITCHB 80
#define TILE_BYTES (128 * PITCHB)            // 10240
#define STAGE_BYTES (2 * TILE_BYTES)         // 20480: A, W
#define GEMM_SMEM (4 * STAGE_BYTES)          // 81920

template <bool RELU, bool RESID, int OUT>
__global__ void __launch_bounds__(128, 2)
gemm_mma(const __half* __restrict__ A, const __half* __restrict__ W,
         const float* __restrict__ bias, float* __restrict__ C,
         __half* __restrict__ Cf,
         __half* __restrict__ Chi, __half* __restrict__ Clo,
         int M, int N, int K) {
    extern __shared__ char smem[];
    uint32_t sb = smem_u32(smem);
    int tid = threadIdx.x, wid = tid >> 5, lane = tid & 31;
    int warp_m = wid & 1, warp_n = wid >> 1;    // 2 x 2 warp grid, 64x64 warp tile
    int row0 = blockIdx.y * 128, col0 = blockIdx.x * 128;

    const int KC = K >> 5;

    float acc[4][8][4];
#pragma unroll
    for (int i = 0; i < 4; i++)
#pragma unroll
        for (int j = 0; j < 8; j++)
#pragma unroll
            for (int q = 0; q < 4; q++) acc[i][j][q] = 0.f;

    uint32_t a_off = (warp_m * 64 + (lane & 15)) * PITCHB + ((lane >> 4) << 4);
    uint32_t b_off = (warp_n * 64 + (lane & 7) + ((lane >> 4) << 3)) * PITCHB + (((lane >> 3) & 1) << 4);

    auto issue = [&](int c) {
        int k0 = c << 5;
        uint32_t base = sb + (c & 3) * STAGE_BYTES;
#pragma unroll
        for (int j = 0; j < 8; j++) {
            int lin = j * 128 + tid;          // 0..1023
            int tile = lin >> 9;              // 0:A 1:W
            int l2 = lin & 511;
            int r = l2 >> 2, seg = l2 & 3;
            const __half* src = tile ? (W + (size_t)(col0 + r) * K)
                                     : (A + (size_t)(row0 + r) * K);
            cpa16(base + tile * TILE_BYTES + r * PITCHB + seg * 16, src + k0 + seg * 8);
        }
        asm volatile("cp.async.commit_group;" ::: "memory");
    };

    issue(0);
    issue(1);
    issue(2);
    for (int c = 0; c < KC; c++) {
        if (c + 2 < KC) {
            asm volatile("cp.async.wait_group 2;" ::: "memory");
        } else if (c + 1 < KC) {
            asm volatile("cp.async.wait_group 1;" ::: "memory");
        } else {
            asm volatile("cp.async.wait_group 0;" ::: "memory");
        }
        __syncthreads();
        if (c + 3 < KC) issue(c + 3);
        uint32_t stage = sb + (c & 3) * STAGE_BYTES;
        uint32_t a_b = stage;
        uint32_t w_b = stage + TILE_BYTES;
#pragma unroll
        for (int ks = 0; ks < 2; ks++) {
            uint32_t bw[4][4];
#pragma unroll
            for (int bt = 0; bt < 4; bt++)
                ldsm4(bw[bt], w_b + b_off + bt * (16 * PITCHB) + ks * 32);
#pragma unroll
            for (int mt = 0; mt < 4; mt++) {
                uint32_t ah[4];
                ldsm4(ah, a_b + a_off + mt * (16 * PITCHB) + ks * 32);
#pragma unroll
                for (int nt = 0; nt < 8; nt++)
                    mma_f16(acc[mt][nt], ah, bw[nt >> 1][(nt & 1) * 2], bw[nt >> 1][(nt & 1) * 2 + 1]);
            }
        }
    }

    int rin = lane >> 2;
    int colp = (lane & 3) * 2;
#pragma unroll
    for (int mt = 0; mt < 4; mt++) {
#pragma unroll
        for (int half = 0; half < 2; half++) {
            int r = row0 + warp_m * 64 + mt * 16 + rin + half * 8;
            size_t rowoff = (size_t)r * N;
#pragma unroll
            for (int nt = 0; nt < 8; nt++) {
                int cg = col0 + warp_n * 64 + nt * 8 + colp;
                float v0 = acc[mt][nt][half * 2 + 0] + bias[cg];
                float v1 = acc[mt][nt][half * 2 + 1] + bias[cg + 1];
                if (RELU) { v0 = fmaxf(v0, 0.f); v1 = fmaxf(v1, 0.f); }
                if (RESID) {
                    float2 o = *(const float2*)&C[rowoff + cg];
                    v0 += o.x; v1 += o.y;
                }
                if (OUT == 0) {
                    *(float2*)&C[rowoff + cg] = make_float2(v0, v1);
                } else if (OUT == 1) {
                    *(uint32_t*)&Cf[rowoff + cg] = packh(v0, v1);
                } else {
                    float s = (cg >= Dd) ? KVSCALE : 1.0f;
                    float y0 = v0 * s, y1 = v1 * s;
                    __half h0 = __float2half(y0), h1 = __float2half(y1);
                    union { __half h[2]; uint32_t u; } ph, pl;
                    ph.h[0] = h0; ph.h[1] = h1;
                    pl.h[0] = __float2half(y0 - __half2float(h0));
                    pl.h[1] = __float2half(y1 - __half2float(h1));
                    *(uint32_t*)&Chi[rowoff + cg] = ph.u;
                    *(uint32_t*)&Clo[rowoff + cg] = pl.u;
                }
            }
        }
    }
}

// ================= HMMA flash attention (fp16 2-pass K/V, Q frags hoisted) =================
#define APB 144
#define SM_Q  0
#define SM_KV 18432
#define KVBUF 36864
#define KVT   9216
#define ATTN_SMEM (18432 + 2 * KVBUF)

__global__ void __launch_bounds__(256, 2)
attn_mma(const __half* __restrict__ qkvhi, const __half* __restrict__ qkvlo,
         const float* __restrict__ amask, __half* __restrict__ ctx) {
    extern __shared__ char sm[];
    uint32_t sb = smem_u32(sm);
    int tid = threadIdx.x, wid = tid >> 5, lane = tid & 31;
    int i0 = blockIdx.x * 128;
    int b = blockIdx.y >> 4, h = blockIdx.y & 15;
    const size_t hq = (size_t)b * Tt * 3 * Dd + h * HD;

#pragma unroll
    for (int j = 0; j < 4; j++) {
        int lin = j * 256 + tid;
        int r = lin >> 3, seg = lin & 7;
        cpa16(sb + SM_Q + r * APB + seg * 16, qkvhi + hq + (size_t)(i0 + r) * 3 * Dd + seg * 8);
    }
    asm volatile("cp.async.commit_group;" ::: "memory");

    int ntiles = i0 / 64 + 2;

    auto issueKV = [&](int jt) {
        int j0 = jt * 64;
        uint32_t buf = sb + SM_KV + (jt & 1) * KVBUF;
#pragma unroll
        for (int j = 0; j < 8; j++) {
            int lin = j * 256 + tid;
            int t = lin >> 9;
            int l = lin & 511;
            int r = l >> 3, seg = l & 7;
            const __half* basep = (t & 1) ? qkvlo : qkvhi;
            int off = (t < 2) ? Dd : 2 * Dd;
            cpa16(buf + t * KVT + r * APB + seg * 16,
                  basep + hq + (size_t)(j0 + r) * 3 * Dd + off + seg * 8);
        }
        asm volatile("cp.async.commit_group;" ::: "memory");
    };

    issueKV(0);

    float o[8][4];
#pragma unroll
    for (int i = 0; i < 8; i++)
#pragma unroll
        for (int q = 0; q < 4; q++) o[i][q] = 0.f;
    float m_run[2] = {-1e30f, -1e30f}, l_run[2] = {0.f, 0.f};

    int r0 = lane >> 2;
    int cq = (lane & 3) * 2;
    int qrow0 = i0 + wid * 16 + r0;
    const float* amrow = amask + b * Tt;
    const float sscale = 0.125f * KVISCALE;

    uint32_t qa_off = (wid * 16 + (lane & 15)) * APB + ((lane >> 4) << 4);
    uint32_t kb_off = ((lane & 7) + ((lane >> 4) << 3)) * APB + (((lane >> 3) & 1) << 4);
    uint32_t vt_off = (lane & 15) * APB + ((lane >> 4) << 4);

    uint32_t qa[4][4];   // Q fragments, loaded once at tile 0

    for (int jt = 0; jt < ntiles; jt++) {
        int j0 = jt * 64;
        bool diag = (j0 + 63 > i0);
        asm volatile("cp.async.wait_group 0;" ::: "memory");
        __syncthreads();
        if (jt + 1 < ntiles) issueKV(jt + 1);
        if (jt == 0) {
#pragma unroll
            for (int s = 0; s < 4; s++)
                ldsm4(qa[s], sb + SM_Q + qa_off + s * 32);
        }

        uint32_t buf = sb + SM_KV + (jt & 1) * KVBUF;
        uint32_t khi_b = buf, klo_b = buf + KVT;
        uint32_t vhi_b = buf + 2 * KVT, vlo_b = buf + 3 * KVT;

        float sf[8][4];
#pragma unroll
        for (int i = 0; i < 8; i++)
#pragma unroll
            for (int q = 0; q < 4; q++) sf[i][q] = 0.f;
#pragma unroll
        for (int pass = 0; pass < 2; pass++) {
            uint32_t kb = (pass ? klo_b : khi_b);
#pragma unroll
            for (int s = 0; s < 4; s++) {
#pragma unroll
                for (int p2 = 0; p2 < 4; p2++) {
                    uint32_t bbq[4];
                    ldsm4(bbq, kb + kb_off + p2 * (16 * APB) + s * 32);
                    mma_f16(sf[p2 * 2], qa[s], bbq[0], bbq[1]);
                    mma_f16(sf[p2 * 2 + 1], qa[s], bbq[2], bbq[3]);
                }
            }
        }

#pragma unroll
        for (int nt = 0; nt < 8; nt++) {
#pragma unroll
            for (int q = 0; q < 4; q++) {
                int col = nt * 8 + cq + (q & 1);
                float am = (1.0f - __ldg(amrow + j0 + col)) * MASK_BIAS;
                float val = sf[nt][q] * sscale;
                if (diag && (j0 + col) > (qrow0 + (q >> 1) * 8)) val = MASK_BIAS;
                sf[nt][q] = val + am;
            }
        }

        float alpha[2];
#pragma unroll
        for (int rh = 0; rh < 2; rh++) {
            float mt = -1e30f;
#pragma unroll
            for (int nt = 0; nt < 8; nt++)
                mt = fmaxf(mt, fmaxf(sf[nt][rh * 2], sf[nt][rh * 2 + 1]));
            mt = fmaxf(mt, __shfl_xor_sync(0xffffffffu, mt, 1));
            mt = fmaxf(mt, __shfl_xor_sync(0xffffffffu, mt, 2));
            float mnew = fmaxf(m_run[rh], mt);
            alpha[rh] = __expf(m_run[rh] - mnew);
            m_run[rh] = mnew;
            float ls = 0.f;
#pragma unroll
            for (int nt = 0; nt < 8; nt++) {
                sf[nt][rh * 2] = __expf(sf[nt][rh * 2] - mnew);
                sf[nt][rh * 2 + 1] = __expf(sf[nt][rh * 2 + 1] - mnew);
                ls += sf[nt][rh * 2] + sf[nt][rh * 2 + 1];
            }
            ls += __shfl_xor_sync(0xffffffffu, ls, 1);
            ls += __shfl_xor_sync(0xffffffffu, ls, 2);
            l_run[rh] = l_run[rh] * alpha[rh] + ls;
        }
#pragma unroll
        for (int nt = 0; nt < 8; nt++) {
            o[nt][0] *= alpha[0]; o[nt][1] *= alpha[0];
            o[nt][2] *= alpha[1]; o[nt][3] *= alpha[1];
        }

#pragma unroll
        for (int s2 = 0; s2 < 4; s2++) {
            uint32_t ph[4];
            ph[0] = packh(sf[2 * s2][0], sf[2 * s2][1]);
            ph[1] = packh(sf[2 * s2][2], sf[2 * s2][3]);
            ph[2] = packh(sf[2 * s2 + 1][0], sf[2 * s2 + 1][1]);
            ph[3] = packh(sf[2 * s2 + 1][2], sf[2 * s2 + 1][3]);
#pragma unroll
            for (int p2 = 0; p2 < 4; p2++) {
                uint32_t vaddr = s2 * (16 * APB) + vt_off + p2 * 32;
                uint32_t bh[4], bl[4];
                ldsm4t(bh, vhi_b + vaddr);
                ldsm4t(bl, vlo_b + vaddr);
                mma_f16(o[p2 * 2], ph, bh[0], bh[1]);
                mma_f16(o[p2 * 2 + 1], ph, bh[2], bh[3]);
                mma_f16(o[p2 * 2], ph, bl[0], bl[1]);
                mma_f16(o[p2 * 2 + 1], ph, bl[2], bl[3]);
            }
        }
    }

    float inv[2] = {KVISCALE / l_run[0], KVISCALE / l_run[1]};
#pragma unroll
    for (int nt = 0; nt < 8; nt++) {
        int d0 = nt * 8 + cq;
#pragma unroll
        for (int rh = 0; rh < 2; rh++) {
            int row = i0 + wid * 16 + r0 + rh * 8;
            size_t off = (size_t)(b * Tt + row) * Dd + h * HD + d0;
            *(uint32_t*)&ctx[off] = packh(o[nt][rh * 2] * inv[rh], o[nt][rh * 2 + 1] * inv[rh]);
        }
    }
}

// ================= host launcher =================
extern "C" void kernel_launch(void* const* d_in, const int* in_sizes, int n_in,
                              void* d_out, int out_size) {
    const float* inputs_embeds = (const float*)d_in[0];
    const float* attention_mask = (const float*)d_in[1];
    const float* ln1_w = (const float*)d_in[2];
    const float* ln1_b = (const float*)d_in[3];
    const float* attn_w = (const float*)d_in[4];
    const float* attn_b = (const float*)d_in[5];
    const float* proj_w = (const float*)d_in[6];
    const float* proj_b = (const float*)d_in[7];
    const float* ln2_w = (const float*)d_in[8];
    const float* ln2_b = (const float*)d_in[9];
    const float* fc_w = (const float*)d_in[10];
    const float* fc_b = (const float*)d_in[11];
    const float* fcp_w = (const float*)d_in[12];
    const float* fcp_b = (const float*)d_in[13];
    const float* lnf_w = (const float*)d_in[14];
    const float* lnf_b = (const float*)d_in[15];
    float* out = (float*)d_out;

    cudaFuncSetAttribute(attn_mma, cudaFuncAttributeMaxDynamicSharedMemorySize, ATTN_SMEM);
    cudaFuncSetAttribute(gemm_mma<false, false, 2>, cudaFuncAttributeMaxDynamicSharedMemorySize, GEMM_SMEM);
    cudaFuncSetAttribute(gemm_mma<false, true, 0>, cudaFuncAttributeMaxDynamicSharedMemorySize, GEMM_SMEM);
    cudaFuncSetAttribute(gemm_mma<true, false, 1>, cudaFuncAttributeMaxDynamicSharedMemorySize, GEMM_SMEM);

    float *ph;
    __half *pqh, *pql, *px16, *pctx, *pff;
    __half *wq, *wp, *wf, *wg;
    cudaGetSymbolAddress((void**)&ph, g_h);
    cudaGetSymbolAddress((void**)&pqh, g_qkvhi);
    cudaGetSymbolAddress((void**)&pql, g_qkvlo);
    cudaGetSymbolAddress((void**)&px16, g_x16);
    cudaGetSymbolAddress((void**)&pctx, g_ctx16);
    cudaGetSymbolAddress((void**)&pff, g_ff16);
    cudaGetSymbolAddress((void**)&wq, g_wqkv);
    cudaGetSymbolAddress((void**)&wp, g_wproj);
    cudaGetSymbolAddress((void**)&wf, g_wfc);
    cudaGetSymbolAddress((void**)&wg, g_wfcp);

    const int MT = Bb * Tt;

    copy_kernel<<<(MT * Dd / 4) / 256, 256>>>(inputs_embeds);

    for (int l = 0; l < Ll; l++) {
        wconv_kernel<<<dim3(3 * Dd / 64, Dd / 64), 256>>>(
            attn_w + (size_t)l * Dd * 3 * Dd, wq + (size_t)l * 3 * Dd * Dd, Dd, 3 * Dd);
        wconv_kernel<<<dim3(Dd / 64, Dd / 64), 256>>>(
            proj_w + (size_t)l * Dd * Dd, wp + (size_t)l * Dd * Dd, Dd, Dd);
        wconv_kernel<<<dim3(II / 64, Dd / 64), 256>>>(
            fc_w + (size_t)l * Dd * II, wf + (size_t)l * II * Dd, Dd, II);
        wconv_kernel<<<dim3(Dd / 64, II / 64), 256>>>(
            fcp_w + (size_t)l * II * Dd, wg + (size_t)l * Dd * II, II, Dd);
    }

    for (int l = 0; l < Ll; l++) {
        ln_kernel<true><<<MT, 256>>>(ph, ln1_w + (size_t)l * Dd, ln1_b + (size_t)l * Dd, nullptr, px16);
        gemm_mma<false, false, 2><<<dim3(3 * Dd / 128, MT / 128), 128, GEMM_SMEM>>>(
            px16, wq + (size_t)l * 3 * Dd * Dd,
            attn_b + (size_t)l * 3 * Dd, nullptr, nullptr, pqh, pql, MT, 3 * Dd, Dd);
        attn_mma<<<dim3(Tt / 128, Bb * Hh), 256, ATTN_SMEM>>>(pqh, pql, attention_mask, pctx);
        gemm_mma<false, true, 0><<<dim3(Dd / 128, MT / 128), 128, GEMM_SMEM>>>(
            pctx, wp + (size_t)l * Dd * Dd,
            proj_b + (size_t)l * Dd, ph, nullptr, nullptr, nullptr, MT, Dd, Dd);
        ln_kernel<true><<<MT, 256>>>(ph, ln2_w + (size_t)l * Dd, ln2_b + (size_t)l * Dd, nullptr, px16);
        gemm_mma<true, false, 1><<<dim3(II / 128, MT / 128), 128, GEMM_SMEM>>>(
            px16, wf + (size_t)l * II * Dd,
            fc_b + (size_t)l * II, nullptr, pff, nullptr, nullptr, MT, II, Dd);
        gemm_mma<false, true, 0><<<dim3(Dd / 128, MT / 128), 128, GEMM_SMEM>>>(
            pff, wg + (size_t)l * Dd * II,
            fcp_b + (size_t)l * Dd, ph, nullptr, nullptr, nullptr, MT, Dd, II);
    }
    ln_kernel<false><<<MT, 256>>>(ph, lnf_w, lnf_b, out, nullptr);
}

// round 16
// speedup vs baseline: 1.0108x; 1.0108x over previous
#include <cuda_runtime.h>
#include <cuda_bf16.h>
#include <cuda_fp16.h>
#include <math.h>
#include <stdint.h>

#define Bb 2
#define Tt 2048
#define Dd 1024
#define Hh 16
#define Ll 8
#define II 4096
#define HD 64
#define MASK_BIAS -10000.0f
#define LN_EPS 1e-5f
#define KVSCALE 64.0f
#define KVISCALE 0.015625f

// ================= scratch =================
__device__ float g_h[Bb * Tt * Dd];
__device__ __half g_qkvhi[Bb * Tt * 3 * Dd], g_qkvlo[Bb * Tt * 3 * Dd];
__device__ __half g_x16[Bb * Tt * Dd];
__device__ __half g_ctx16[Bb * Tt * Dd];
__device__ __half g_ff16[Bb * Tt * II];
// transposed fp16 weight slabs [L][N][K]
__device__ __half g_wqkv[Ll * 3 * Dd * Dd];
__device__ __half g_wproj[Ll * Dd * Dd];
__device__ __half g_wfc[Ll * II * Dd];
__device__ __half g_wfcp[Ll * Dd * II];

__device__ __forceinline__ uint32_t smem_u32(const void* p) {
    uint32_t a;
    asm("{ .reg .u64 t; cvta.to.shared.u64 t, %1; cvt.u32.u64 %0, t; }" : "=r"(a) : "l"(p));
    return a;
}
__device__ __forceinline__ void ldsm4(uint32_t* r, uint32_t addr) {
    asm volatile("ldmatrix.sync.aligned.m8n8.x4.shared.b16 {%0,%1,%2,%3}, [%4];"
                 : "=r"(r[0]), "=r"(r[1]), "=r"(r[2]), "=r"(r[3]) : "r"(addr));
}
__device__ __forceinline__ void ldsm4t(uint32_t* r, uint32_t addr) {
    asm volatile("ldmatrix.sync.aligned.m8n8.x4.trans.shared.b16 {%0,%1,%2,%3}, [%4];"
                 : "=r"(r[0]), "=r"(r[1]), "=r"(r[2]), "=r"(r[3]) : "r"(addr));
}
__device__ __forceinline__ void mma_f16(float* d, const uint32_t* a, uint32_t b0, uint32_t b1) {
    asm volatile("mma.sync.aligned.m16n8k16.row.col.f32.f16.f16.f32 "
                 "{%0,%1,%2,%3}, {%4,%5,%6,%7}, {%8,%9}, {%0,%1,%2,%3};"
                 : "+f"(d[0]), "+f"(d[1]), "+f"(d[2]), "+f"(d[3])
                 : "r"(a[0]), "r"(a[1]), "r"(a[2]), "r"(a[3]), "r"(b0), "r"(b1));
}
__device__ __forceinline__ uint32_t packh(float x, float y) {
    __half2 t = __floats2half2_rn(x, y);
    return *reinterpret_cast<uint32_t*>(&t);
}
__device__ __forceinline__ void cpa16(uint32_t s, const void* g) {
    asm volatile("cp.async.cg.shared.global [%0], [%1], 16;" :: "r"(s), "l"(g));
}

// ================= small kernels =================
__global__ void copy_kernel(const float* __restrict__ src) {
    int i = blockIdx.x * blockDim.x + threadIdx.x;
    reinterpret_cast<float4*>(g_h)[i] = reinterpret_cast<const float4*>(src)[i];
}

// weight transpose + fp16 convert: W[K][N] -> W'[N][K], 64x64 tiles, vectorized
__global__ void wconv_kernel(const float* __restrict__ W, __half* __restrict__ Wo,
                             int K, int N) {
    __shared__ float s[64][65];
    int n0 = blockIdx.x * 64, k0 = blockIdx.y * 64;
    int tid = threadIdx.x;
    int lr = tid >> 4;          // 0..15
    int lc = (tid & 15) * 4;    // 0..60
#pragma unroll
    for (int i = 0; i < 4; i++) {
        int k = lr + i * 16;
        float4 v = *(const float4*)&W[(size_t)(k0 + k) * N + n0 + lc];
        s[k][lc] = v.x; s[k][lc + 1] = v.y; s[k][lc + 2] = v.z; s[k][lc + 3] = v.w;
    }
    __syncthreads();
    int n = tid >> 2;           // 0..63
    int ks = (tid & 3) * 16;    // 0,16,32,48
    union { __half h[16]; uint4 u[2]; } o;
#pragma unroll
    for (int j = 0; j < 16; j++) o.h[j] = __float2half(s[ks + j][n]);
    uint4* dst = (uint4*)&Wo[(size_t)(n0 + n) * K + k0 + ks];
    dst[0] = o.u[0];
    dst[1] = o.u[1];
}

template <bool F16OUT>
__global__ void ln_kernel(const float* __restrict__ x, const float* __restrict__ w,
                          const float* __restrict__ b, float* __restrict__ out,
                          __half* __restrict__ o16) {
    int row = blockIdx.x;
    int tid = threadIdx.x;
    const float* xr = x + (size_t)row * Dd;
    float4 v = *(const float4*)&xr[tid * 4];
    float sum = v.x + v.y + v.z + v.w;
    float sq = v.x * v.x + v.y * v.y + v.z * v.z + v.w * v.w;
#pragma unroll
    for (int o = 16; o > 0; o >>= 1) {
        sum += __shfl_xor_sync(0xffffffffu, sum, o);
        sq += __shfl_xor_sync(0xffffffffu, sq, o);
    }
    __shared__ float ssum[8], ssq[8], stat[2];
    if ((tid & 31) == 0) { ssum[tid >> 5] = sum; ssq[tid >> 5] = sq; }
    __syncthreads();
    if (tid == 0) {
        float S = 0.f, Q = 0.f;
#pragma unroll
        for (int i = 0; i < 8; i++) { S += ssum[i]; Q += ssq[i]; }
        float mean = S * (1.0f / Dd);
        float var = Q * (1.0f / Dd) - mean * mean;
        stat[0] = mean;
        stat[1] = rsqrtf(var + LN_EPS);
    }
    __syncthreads();
    float mean = stat[0], rstd = stat[1];
    int c = tid * 4;
    float4 wv = *(const float4*)&w[c];
    float4 bv = *(const float4*)&b[c];
    float y0 = (v.x - mean) * rstd * wv.x + bv.x;
    float y1 = (v.y - mean) * rstd * wv.y + bv.y;
    float y2 = (v.z - mean) * rstd * wv.z + bv.z;
    float y3 = (v.w - mean) * rstd * wv.w + bv.w;
    if (F16OUT) {
        uint2 o;
        o.x = packh(y0, y1);
        o.y = packh(y2, y3);
        *(uint2*)&o16[(size_t)row * Dd + c] = o;
    } else {
        *(float4*)&out[(size_t)row * Dd + c] = make_float4(y0, y1, y2, y3);
    }
}

// ================= HMMA GEMM (fp16, 64x64 warp tile, 128 thr, 3-stage, 2 CTAs/SM) =================
// OUT: 0 = fp32 C, 1 = fp16 Cf, 2 = fp16 hi/lo qkv (K/V cols x64-scaled)
#define PITCHB 80
#define TILE_BYTES (128 * PITCHB)            // 10240
#define STAGE_BYTES (2 * TILE_BYTES)         // 20480: A, W
#define GEMM_SMEM (3 * STAGE_BYTES)          // 61440

template <bool RELU, bool RESID, int OUT>
__global__ void __launch_bounds__(128, 2)
gemm_mma(const __half* __restrict__ A, const __half* __restrict__ W,
         const float* __restrict__ bias, float* __restrict__ C,
         __half* __restrict__ Cf,
         __half* __restrict__ Chi, __half* __restrict__ Clo,
         int M, int N, int K) {
    extern __shared__ char smem[];
    uint32_t sb = smem_u32(smem);
    int tid = threadIdx.x, wid = tid >> 5, lane = tid & 31;
    int warp_m = wid & 1, warp_n = wid >> 1;    // 2 x 2 warp grid, 64x64 warp tile
    int row0 = blockIdx.y * 128, col0 = blockIdx.x * 128;

    const int KC = K >> 5;

    float acc[4][8][4];
#pragma unroll
    for (int i = 0; i < 4; i++)
#pragma unroll
        for (int j = 0; j < 8; j++)
#pragma unroll
            for (int q = 0; q < 4; q++) acc[i][j][q] = 0.f;

    uint32_t a_off = (warp_m * 64 + (lane & 15)) * PITCHB + ((lane >> 4) << 4);
    uint32_t b_off = (warp_n * 64 + (lane & 7) + ((lane >> 4) << 3)) * PITCHB + (((lane >> 3) & 1) << 4);

    auto issue = [&](int c) {
        int k0 = c << 5;
        uint32_t base = sb + (c % 3) * STAGE_BYTES;
#pragma unroll
        for (int j = 0; j < 8; j++) {
            int lin = j * 128 + tid;          // 0..1023
            int tile = lin >> 9;              // 0:A 1:W
            int l2 = lin & 511;
            int r = l2 >> 2, seg = l2 & 3;
            const __half* src = tile ? (W + (size_t)(col0 + r) * K)
                                     : (A + (size_t)(row0 + r) * K);
            cpa16(base + tile * TILE_BYTES + r * PITCHB + seg * 16, src + k0 + seg * 8);
        }
        asm volatile("cp.async.commit_group;" ::: "memory");
    };

    issue(0);
    issue(1);
    for (int c = 0; c < KC; c++) {
        if (c + 1 < KC) {
            asm volatile("cp.async.wait_group 1;" ::: "memory");
        } else {
            asm volatile("cp.async.wait_group 0;" ::: "memory");
        }
        __syncthreads();
        if (c + 2 < KC) issue(c + 2);
        uint32_t stage = sb + (c % 3) * STAGE_BYTES;
        uint32_t a_b = stage;
        uint32_t w_b = stage + TILE_BYTES;
#pragma unroll
        for (int ks = 0; ks < 2; ks++) {
            uint32_t bw[4][4];
#pragma unroll
            for (int bt = 0; bt < 4; bt++)
                ldsm4(bw[bt], w_b + b_off + bt * (16 * PITCHB) + ks * 32);
#pragma unroll
            for (int mt = 0; mt < 4; mt++) {
                uint32_t ah[4];
                ldsm4(ah, a_b + a_off + mt * (16 * PITCHB) + ks * 32);
#pragma unroll
                for (int nt = 0; nt < 8; nt++)
                    mma_f16(acc[mt][nt], ah, bw[nt >> 1][(nt & 1) * 2], bw[nt >> 1][(nt & 1) * 2 + 1]);
            }
        }
    }

    int rin = lane >> 2;
    int colp = (lane & 3) * 2;
#pragma unroll
    for (int mt = 0; mt < 4; mt++) {
#pragma unroll
        for (int half = 0; half < 2; half++) {
            int r = row0 + warp_m * 64 + mt * 16 + rin + half * 8;
            size_t rowoff = (size_t)r * N;
#pragma unroll
            for (int nt = 0; nt < 8; nt++) {
                int cg = col0 + warp_n * 64 + nt * 8 + colp;
                float v0 = acc[mt][nt][half * 2 + 0] + bias[cg];
                float v1 = acc[mt][nt][half * 2 + 1] + bias[cg + 1];
                if (RELU) { v0 = fmaxf(v0, 0.f); v1 = fmaxf(v1, 0.f); }
                if (RESID) {
                    float2 o = *(const float2*)&C[rowoff + cg];
                    v0 += o.x; v1 += o.y;
                }
                if (OUT == 0) {
                    *(float2*)&C[rowoff + cg] = make_float2(v0, v1);
                } else if (OUT == 1) {
                    *(uint32_t*)&Cf[rowoff + cg] = packh(v0, v1);
                } else {
                    float s = (cg >= Dd) ? KVSCALE : 1.0f;
                    float y0 = v0 * s, y1 = v1 * s;
                    __half h0 = __float2half(y0), h1 = __float2half(y1);
                    union { __half h[2]; uint32_t u; } ph, pl;
                    ph.h[0] = h0; ph.h[1] = h1;
                    pl.h[0] = __float2half(y0 - __half2float(h0));
                    pl.h[1] = __float2half(y1 - __half2float(h1));
                    *(uint32_t*)&Chi[rowoff + cg] = ph.u;
                    *(uint32_t*)&Clo[rowoff + cg] = pl.u;
                }
            }
        }
    }
}

// ================= HMMA flash attention (fp16 2-pass K/V, Q frags hoisted) =================
#define APB 144
#define SM_Q  0
#define SM_KV 18432
#define KVBUF 36864
#define KVT   9216
#define ATTN_SMEM (18432 + 2 * KVBUF)

__global__ void __launch_bounds__(256, 2)
attn_mma(const __half* __restrict__ qkvhi, const __half* __restrict__ qkvlo,
         const float* __restrict__ amask, __half* __restrict__ ctx) {
    extern __shared__ char sm[];
    uint32_t sb = smem_u32(sm);
    int tid = threadIdx.x, wid = tid >> 5, lane = tid & 31;
    int i0 = blockIdx.x * 128;
    int b = blockIdx.y >> 4, h = blockIdx.y & 15;
    const size_t hq = (size_t)b * Tt * 3 * Dd + h * HD;

#pragma unroll
    for (int j = 0; j < 4; j++) {
        int lin = j * 256 + tid;
        int r = lin >> 3, seg = lin & 7;
        cpa16(sb + SM_Q + r * APB + seg * 16, qkvhi + hq + (size_t)(i0 + r) * 3 * Dd + seg * 8);
    }
    asm volatile("cp.async.commit_group;" ::: "memory");

    int ntiles = i0 / 64 + 2;

    auto issueKV = [&](int jt) {
        int j0 = jt * 64;
        uint32_t buf = sb + SM_KV + (jt & 1) * KVBUF;
#pragma unroll
        for (int j = 0; j < 8; j++) {
            int lin = j * 256 + tid;
            int t = lin >> 9;
            int l = lin & 511;
            int r = l >> 3, seg = l & 7;
            const __half* basep = (t & 1) ? qkvlo : qkvhi;
            int off = (t < 2) ? Dd : 2 * Dd;
            cpa16(buf + t * KVT + r * APB + seg * 16,
                  basep + hq + (size_t)(j0 + r) * 3 * Dd + off + seg * 8);
        }
        asm volatile("cp.async.commit_group;" ::: "memory");
    };

    issueKV(0);

    float o[8][4];
#pragma unroll
    for (int i = 0; i < 8; i++)
#pragma unroll
        for (int q = 0; q < 4; q++) o[i][q] = 0.f;
    float m_run[2] = {-1e30f, -1e30f}, l_run[2] = {0.f, 0.f};

    int r0 = lane >> 2;
    int cq = (lane & 3) * 2;
    int qrow0 = i0 + wid * 16 + r0;
    const float* amrow = amask + b * Tt;
    const float sscale = 0.125f * KVISCALE;

    uint32_t qa_off = (wid * 16 + (lane & 15)) * APB + ((lane >> 4) << 4);
    uint32_t kb_off = ((lane & 7) + ((lane >> 4) << 3)) * APB + (((lane >> 3) & 1) << 4);
    uint32_t vt_off = (lane & 15) * APB + ((lane >> 4) << 4);

    uint32_t qa[4][4];   // Q fragments, loaded once at tile 0

    for (int jt = 0; jt < ntiles; jt++) {
        int j0 = jt * 64;
        bool diag = (j0 + 63 > i0);
        asm volatile("cp.async.wait_group 0;" ::: "memory");
        __syncthreads();
        if (jt + 1 < ntiles) issueKV(jt + 1);
        if (jt == 0) {
#pragma unroll
            for (int s = 0; s < 4; s++)
                ldsm4(qa[s], sb + SM_Q + qa_off + s * 32);
        }

        uint32_t buf = sb + SM_KV + (jt & 1) * KVBUF;
        uint32_t khi_b = buf, klo_b = buf + KVT;
        uint32_t vhi_b = buf + 2 * KVT, vlo_b = buf + 3 * KVT;

        float sf[8][4];
#pragma unroll
        for (int i = 0; i < 8; i++)
#pragma unroll
            for (int q = 0; q < 4; q++) sf[i][q] = 0.f;
#pragma unroll
        for (int pass = 0; pass < 2; pass++) {
            uint32_t kb = (pass ? klo_b : khi_b);
#pragma unroll
            for (int s = 0; s < 4; s++) {
#pragma unroll
                for (int p2 = 0; p2 < 4; p2++) {
                    uint32_t bbq[4];
                    ldsm4(bbq, kb + kb_off + p2 * (16 * APB) + s * 32);
                    mma_f16(sf[p2 * 2], qa[s], bbq[0], bbq[1]);
                    mma_f16(sf[p2 * 2 + 1], qa[s], bbq[2], bbq[3]);
                }
            }
        }

#pragma unroll
        for (int nt = 0; nt < 8; nt++) {
#pragma unroll
            for (int q = 0; q < 4; q++) {
                int col = nt * 8 + cq + (q & 1);
                float am = (1.0f - __ldg(amrow + j0 + col)) * MASK_BIAS;
                float val = sf[nt][q] * sscale;
                if (diag && (j0 + col) > (qrow0 + (q >> 1) * 8)) val = MASK_BIAS;
                sf[nt][q] = val + am;
            }
        }

        float alpha[2];
#pragma unroll
        for (int rh = 0; rh < 2; rh++) {
            float mt = -1e30f;
#pragma unroll
            for (int nt = 0; nt < 8; nt++)
                mt = fmaxf(mt, fmaxf(sf[nt][rh * 2], sf[nt][rh * 2 + 1]));
            mt = fmaxf(mt, __shfl_xor_sync(0xffffffffu, mt, 1));
            mt = fmaxf(mt, __shfl_xor_sync(0xffffffffu, mt, 2));
            float mnew = fmaxf(m_run[rh], mt);
            alpha[rh] = __expf(m_run[rh] - mnew);
            m_run[rh] = mnew;
            float ls = 0.f;
#pragma unroll
            for (int nt = 0; nt < 8; nt++) {
                sf[nt][rh * 2] = __expf(sf[nt][rh * 2] - mnew);
                sf[nt][rh * 2 + 1] = __expf(sf[nt][rh * 2 + 1] - mnew);
                ls += sf[nt][rh * 2] + sf[nt][rh * 2 + 1];
            }
            ls += __shfl_xor_sync(0xffffffffu, ls, 1);
            ls += __shfl_xor_sync(0xffffffffu, ls, 2);
            l_run[rh] = l_run[rh] * alpha[rh] + ls;
        }
#pragma unroll
        for (int nt = 0; nt < 8; nt++) {
            o[nt][0] *= alpha[0]; o[nt][1] *= alpha[0];
            o[nt][2] *= alpha[1]; o[nt][3] *= alpha[1];
        }

#pragma unroll
        for (int s2 = 0; s2 < 4; s2++) {
            uint32_t ph[4];
            ph[0] = packh(sf[2 * s2][0], sf[2 * s2][1]);
            ph[1] = packh(sf[2 * s2][2], sf[2 * s2][3]);
            ph[2] = packh(sf[2 * s2 + 1][0], sf[2 * s2 + 1][1]);
            ph[3] = packh(sf[2 * s2 + 1][2], sf[2 * s2 + 1][3]);
#pragma unroll
            for (int p2 = 0; p2 < 4; p2++) {
                uint32_t vaddr = s2 * (16 * APB) + vt_off + p2 * 32;
                uint32_t bh[4], bl[4];
                ldsm4t(bh, vhi_b + vaddr);
                ldsm4t(bl, vlo_b + vaddr);
                mma_f16(o[p2 * 2], ph, bh[0], bh[1]);
                mma_f16(o[p2 * 2 + 1], ph, bh[2], bh[3]);
                mma_f16(o[p2 * 2], ph, bl[0], bl[1]);
                mma_f16(o[p2 * 2 + 1], ph, bl[2], bl[3]);
            }
        }
    }

    float inv[2] = {KVISCALE / l_run[0], KVISCALE / l_run[1]};
#pragma unroll
    for (int nt = 0; nt < 8; nt++) {
        int d0 = nt * 8 + cq;
#pragma unroll
        for (int rh = 0; rh < 2; rh++) {
            int row = i0 + wid * 16 + r0 + rh * 8;
            size_t off = (size_t)(b * Tt + row) * Dd + h * HD + d0;
            *(uint32_t*)&ctx[off] = packh(o[nt][rh * 2] * inv[rh], o[nt][rh * 2 + 1] * inv[rh]);
        }
    }
}

// ================= host launcher =================
extern "C" void kernel_launch(void* const* d_in, const int* in_sizes, int n_in,
                              void* d_out, int out_size) {
    const float* inputs_embeds = (const float*)d_in[0];
    const float* attention_mask = (const float*)d_in[1];
    const float* ln1_w = (const float*)d_in[2];
    const float* ln1_b = (const float*)d_in[3];
    const float* attn_w = (const float*)d_in[4];
    const float* attn_b = (const float*)d_in[5];
    const float* proj_w = (const float*)d_in[6];
    const float* proj_b = (const float*)d_in[7];
    const float* ln2_w = (const float*)d_in[8];
    const float* ln2_b = (const float*)d_in[9];
    const float* fc_w = (const float*)d_in[10];
    const float* fc_b = (const float*)d_in[11];
    const float* fcp_w = (const float*)d_in[12];
    const float* fcp_b = (const float*)d_in[13];
    const float* lnf_w = (const float*)d_in[14];
    const float* lnf_b = (const float*)d_in[15];
    float* out = (float*)d_out;

    cudaFuncSetAttribute(attn_mma, cudaFuncAttributeMaxDynamicSharedMemorySize, ATTN_SMEM);
    cudaFuncSetAttribute(gemm_mma<false, false, 2>, cudaFuncAttributeMaxDynamicSharedMemorySize, GEMM_SMEM);
    cudaFuncSetAttribute(gemm_mma<false, true, 0>, cudaFuncAttributeMaxDynamicSharedMemorySize, GEMM_SMEM);
    cudaFuncSetAttribute(gemm_mma<true, false, 1>, cudaFuncAttributeMaxDynamicSharedMemorySize, GEMM_SMEM);

    float *ph;
    __half *pqh, *pql, *px16, *pctx, *pff;
    __half *wq, *wp, *wf, *wg;
    cudaGetSymbolAddress((void**)&ph, g_h);
    cudaGetSymbolAddress((void**)&pqh, g_qkvhi);
    cudaGetSymbolAddress((void**)&pql, g_qkvlo);
    cudaGetSymbolAddress((void**)&px16, g_x16);
    cudaGetSymbolAddress((void**)&pctx, g_ctx16);
    cudaGetSymbolAddress((void**)&pff, g_ff16);
    cudaGetSymbolAddress((void**)&wq, g_wqkv);
    cudaGetSymbolAddress((void**)&wp, g_wproj);
    cudaGetSymbolAddress((void**)&wf, g_wfc);
    cudaGetSymbolAddress((void**)&wg, g_wfcp);

    const int MT = Bb * Tt;

    copy_kernel<<<(MT * Dd / 4) / 256, 256>>>(inputs_embeds);

    for (int l = 0; l < Ll; l++) {
        wconv_kernel<<<dim3(3 * Dd / 64, Dd / 64), 256>>>(
            attn_w + (size_t)l * Dd * 3 * Dd, wq + (size_t)l * 3 * Dd * Dd, Dd, 3 * Dd);
        wconv_kernel<<<dim3(Dd / 64, Dd / 64), 256>>>(
            proj_w + (size_t)l * Dd * Dd, wp + (size_t)l * Dd * Dd, Dd, Dd);
        wconv_kernel<<<dim3(II / 64, Dd / 64), 256>>>(
            fc_w + (size_t)l * Dd * II, wf + (size_t)l * II * Dd, Dd, II);
        wconv_kernel<<<dim3(Dd / 64, II / 64), 256>>>(
            fcp_w + (size_t)l * II * Dd, wg + (size_t)l * Dd * II, II, Dd);
    }

    for (int l = 0; l < Ll; l++) {
        ln_kernel<true><<<MT, 256>>>(ph, ln1_w + (size_t)l * Dd, ln1_b + (size_t)l * Dd, nullptr, px16);
        gemm_mma<false, false, 2><<<dim3(3 * Dd / 128, MT / 128), 128, GEMM_SMEM>>>(
            px16, wq + (size_t)l * 3 * Dd * Dd,
            attn_b + (size_t)l * 3 * Dd, nullptr, nullptr, pqh, pql, MT, 3 * Dd, Dd);
        attn_mma<<<dim3(Tt / 128, Bb * Hh), 256, ATTN_SMEM>>>(pqh, pql, attention_mask, pctx);
        gemm_mma<false, true, 0><<<dim3(Dd / 128, MT / 128), 128, GEMM_SMEM>>>(
            pctx, wp + (size_t)l * Dd * Dd,
            proj_b + (size_t)l * Dd, ph, nullptr, nullptr, nullptr, MT, Dd, Dd);
        ln_kernel<true><<<MT, 256>>>(ph, ln2_w + (size_t)l * Dd, ln2_b + (size_t)l * Dd, nullptr, px16);
        gemm_mma<true, false, 1><<<dim3(II / 128, MT / 128), 128, GEMM_SMEM>>>(
            px16, wf + (size_t)l * II * Dd,
            fc_b + (size_t)l * II, nullptr, pff, nullptr, nullptr, MT, II, Dd);
        gemm_mma<false, true, 0><<<dim3(Dd / 128, MT / 128), 128, GEMM_SMEM>>>(
            pff, wg + (size_t)l * Dd * II,
            fcp_b + (size_t)l * Dd, ph, nullptr, nullptr, nullptr, MT, Dd, II);
    }
    ln_kernel<false><<<MT, 256>>>(ph, lnf_w, lnf_b, out, nullptr);
}

// round 17
// speedup vs baseline: 1.0359x; 1.0249x over previous
#include <cuda_runtime.h>
#include <cuda_bf16.h>
#include <cuda_fp16.h>
#include <math.h>
#include <stdint.h>

#define Bb 2
#define Tt 2048
#define Dd 1024
#define Hh 16
#define Ll 8
#define II 4096
#define HD 64
#define MASK_BIAS -10000.0f
#define LN_EPS 1e-5f
#define KVSCALE 64.0f
#define KVISCALE 0.015625f

// ================= scratch =================
__device__ float g_h[Bb * Tt * Dd];
__device__ __half g_qkvhi[Bb * Tt * 3 * Dd], g_qkvlo[Bb * Tt * 3 * Dd];
__device__ __half g_x16[Bb * Tt * Dd];
__device__ __half g_ctx16[Bb * Tt * Dd];
__device__ __half g_ff16[Bb * Tt * II];
// transposed fp16 weight slabs [L][N][K]
__device__ __half g_wqkv[Ll * 3 * Dd * Dd];
__device__ __half g_wproj[Ll * Dd * Dd];
__device__ __half g_wfc[Ll * II * Dd];
__device__ __half g_wfcp[Ll * Dd * II];

__device__ __forceinline__ uint32_t smem_u32(const void* p) {
    uint32_t a;
    asm("{ .reg .u64 t; cvta.to.shared.u64 t, %1; cvt.u32.u64 %0, t; }" : "=r"(a) : "l"(p));
    return a;
}
__device__ __forceinline__ void ldsm4(uint32_t* r, uint32_t addr) {
    asm volatile("ldmatrix.sync.aligned.m8n8.x4.shared.b16 {%0,%1,%2,%3}, [%4];"
                 : "=r"(r[0]), "=r"(r[1]), "=r"(r[2]), "=r"(r[3]) : "r"(addr));
}
__device__ __forceinline__ void ldsm4t(uint32_t* r, uint32_t addr) {
    asm volatile("ldmatrix.sync.aligned.m8n8.x4.trans.shared.b16 {%0,%1,%2,%3}, [%4];"
                 : "=r"(r[0]), "=r"(r[1]), "=r"(r[2]), "=r"(r[3]) : "r"(addr));
}
__device__ __forceinline__ void mma_f16(float* d, const uint32_t* a, uint32_t b0, uint32_t b1) {
    asm volatile("mma.sync.aligned.m16n8k16.row.col.f32.f16.f16.f32 "
                 "{%0,%1,%2,%3}, {%4,%5,%6,%7}, {%8,%9}, {%0,%1,%2,%3};"
                 : "+f"(d[0]), "+f"(d[1]), "+f"(d[2]), "+f"(d[3])
                 : "r"(a[0]), "r"(a[1]), "r"(a[2]), "r"(a[3]), "r"(b0), "r"(b1));
}
__device__ __forceinline__ uint32_t packh(float x, float y) {
    __half2 t = __floats2half2_rn(x, y);
    return *reinterpret_cast<uint32_t*>(&t);
}
__device__ __forceinline__ void cpa16(uint32_t s, const void* g) {
    asm volatile("cp.async.cg.shared.global [%0], [%1], 16;" :: "r"(s), "l"(g));
}

// ================= small kernels =================
__global__ void copy_kernel(const float* __restrict__ src) {
    int i = blockIdx.x * blockDim.x + threadIdx.x;
    reinterpret_cast<float4*>(g_h)[i] = reinterpret_cast<const float4*>(src)[i];
}

// weight transpose + fp16 convert: W[K][N] -> W'[N][K], 64x64 tiles, batched over layers (blockIdx.z)
__global__ void wconv_kernel(const float* __restrict__ W, __half* __restrict__ Wo,
                             int K, int N) {
    __shared__ float s[64][65];
    int l = blockIdx.z;
    const float* Wl = W + (size_t)l * K * N;
    __half* Wol = Wo + (size_t)l * K * N;
    int n0 = blockIdx.x * 64, k0 = blockIdx.y * 64;
    int tid = threadIdx.x;
    int lr = tid >> 4;          // 0..15
    int lc = (tid & 15) * 4;    // 0..60
#pragma unroll
    for (int i = 0; i < 4; i++) {
        int k = lr + i * 16;
        float4 v = *(const float4*)&Wl[(size_t)(k0 + k) * N + n0 + lc];
        s[k][lc] = v.x; s[k][lc + 1] = v.y; s[k][lc + 2] = v.z; s[k][lc + 3] = v.w;
    }
    __syncthreads();
    int n = tid >> 2;           // 0..63
    int ks = (tid & 3) * 16;    // 0,16,32,48
    union { __half h[16]; uint4 u[2]; } o;
#pragma unroll
    for (int j = 0; j < 16; j++) o.h[j] = __float2half(s[ks + j][n]);
    uint4* dst = (uint4*)&Wol[(size_t)(n0 + n) * K + k0 + ks];
    dst[0] = o.u[0];
    dst[1] = o.u[1];
}

template <bool F16OUT>
__global__ void ln_kernel(const float* __restrict__ x, const float* __restrict__ w,
                          const float* __restrict__ b, float* __restrict__ out,
                          __half* __restrict__ o16) {
    int row = blockIdx.x;
    int tid = threadIdx.x;
    const float* xr = x + (size_t)row * Dd;
    float4 v = *(const float4*)&xr[tid * 4];
    float sum = v.x + v.y + v.z + v.w;
    float sq = v.x * v.x + v.y * v.y + v.z * v.z + v.w * v.w;
#pragma unroll
    for (int o = 16; o > 0; o >>= 1) {
        sum += __shfl_xor_sync(0xffffffffu, sum, o);
        sq += __shfl_xor_sync(0xffffffffu, sq, o);
    }
    __shared__ float ssum[8], ssq[8], stat[2];
    if ((tid & 31) == 0) { ssum[tid >> 5] = sum; ssq[tid >> 5] = sq; }
    __syncthreads();
    if (tid == 0) {
        float S = 0.f, Q = 0.f;
#pragma unroll
        for (int i = 0; i < 8; i++) { S += ssum[i]; Q += ssq[i]; }
        float mean = S * (1.0f / Dd);
        float var = Q * (1.0f / Dd) - mean * mean;
        stat[0] = mean;
        stat[1] = rsqrtf(var + LN_EPS);
    }
    __syncthreads();
    float mean = stat[0], rstd = stat[1];
    int c = tid * 4;
    float4 wv = *(const float4*)&w[c];
    float4 bv = *(const float4*)&b[c];
    float y0 = (v.x - mean) * rstd * wv.x + bv.x;
    float y1 = (v.y - mean) * rstd * wv.y + bv.y;
    float y2 = (v.z - mean) * rstd * wv.z + bv.z;
    float y3 = (v.w - mean) * rstd * wv.w + bv.w;
    if (F16OUT) {
        uint2 o;
        o.x = packh(y0, y1);
        o.y = packh(y2, y3);
        *(uint2*)&o16[(size_t)row * Dd + c] = o;
    } else {
        *(float4*)&out[(size_t)row * Dd + c] = make_float4(y0, y1, y2, y3);
    }
}

// ================= HMMA GEMM (fp16, 64x64 warp tile, 128 thr, 3-stage, 2 CTAs/SM) =================
// OUT: 0 = fp32 C, 1 = fp16 Cf, 2 = fp16 hi/lo qkv (K/V cols x64-scaled)
#define PITCHB 80
#define TILE_BYTES (128 * PITCHB)            // 10240
#define STAGE_BYTES (2 * TILE_BYTES)         // 20480: A, W
#define GEMM_SMEM (3 * STAGE_BYTES)          // 61440

template <bool RELU, bool RESID, int OUT>
__global__ void __launch_bounds__(128, 2)
gemm_mma(const __half* __restrict__ A, const __half* __restrict__ W,
         const float* __restrict__ bias, float* __restrict__ C,
         __half* __restrict__ Cf,
         __half* __restrict__ Chi, __half* __restrict__ Clo,
         int M, int N, int K) {
    extern __shared__ char smem[];
    uint32_t sb = smem_u32(smem);
    int tid = threadIdx.x, wid = tid >> 5, lane = tid & 31;
    int warp_m = wid & 1, warp_n = wid >> 1;    // 2 x 2 warp grid, 64x64 warp tile
    int row0 = blockIdx.y * 128, col0 = blockIdx.x * 128;

    const int KC = K >> 5;

    float acc[4][8][4];
#pragma unroll
    for (int i = 0; i < 4; i++)
#pragma unroll
        for (int j = 0; j < 8; j++)
#pragma unroll
            for (int q = 0; q < 4; q++) acc[i][j][q] = 0.f;

    uint32_t a_off = (warp_m * 64 + (lane & 15)) * PITCHB + ((lane >> 4) << 4);
    uint32_t b_off = (warp_n * 64 + (lane & 7) + ((lane >> 4) << 3)) * PITCHB + (((lane >> 3) & 1) << 4);

    auto issue = [&](int c) {
        int k0 = c << 5;
        uint32_t base = sb + (c % 3) * STAGE_BYTES;
#pragma unroll
        for (int j = 0; j < 8; j++) {
            int lin = j * 128 + tid;          // 0..1023
            int tile = lin >> 9;              // 0:A 1:W
            int l2 = lin & 511;
            int r = l2 >> 2, seg = l2 & 3;
            const __half* src = tile ? (W + (size_t)(col0 + r) * K)
                                     : (A + (size_t)(row0 + r) * K);
            cpa16(base + tile * TILE_BYTES + r * PITCHB + seg * 16, src + k0 + seg * 8);
        }
        asm volatile("cp.async.commit_group;" ::: "memory");
    };

    issue(0);
    issue(1);
    for (int c = 0; c < KC; c++) {
        if (c + 1 < KC) {
            asm volatile("cp.async.wait_group 1;" ::: "memory");
        } else {
            asm volatile("cp.async.wait_group 0;" ::: "memory");
        }
        __syncthreads();
        if (c + 2 < KC) issue(c + 2);
        uint32_t stage = sb + (c % 3) * STAGE_BYTES;
        uint32_t a_b = stage;
        uint32_t w_b = stage + TILE_BYTES;
#pragma unroll
        for (int ks = 0; ks < 2; ks++) {
            uint32_t bw[4][4];
#pragma unroll
            for (int bt = 0; bt < 4; bt++)
                ldsm4(bw[bt], w_b + b_off + bt * (16 * PITCHB) + ks * 32);
#pragma unroll
            for (int mt = 0; mt < 4; mt++) {
                uint32_t ah[4];
                ldsm4(ah, a_b + a_off + mt * (16 * PITCHB) + ks * 32);
#pragma unroll
                for (int nt = 0; nt < 8; nt++)
                    mma_f16(acc[mt][nt], ah, bw[nt >> 1][(nt & 1) * 2], bw[nt >> 1][(nt & 1) * 2 + 1]);
            }
        }
    }

    int rin = lane >> 2;
    int colp = (lane & 3) * 2;
#pragma unroll
    for (int mt = 0; mt < 4; mt++) {
#pragma unroll
        for (int half = 0; half < 2; half++) {
            int r = row0 + warp_m * 64 + mt * 16 + rin + half * 8;
            size_t rowoff = (size_t)r * N;
#pragma unroll
            for (int nt = 0; nt < 8; nt++) {
                int cg = col0 + warp_n * 64 + nt * 8 + colp;
                float v0 = acc[mt][nt][half * 2 + 0] + bias[cg];
                float v1 = acc[mt][nt][half * 2 + 1] + bias[cg + 1];
                if (RELU) { v0 = fmaxf(v0, 0.f); v1 = fmaxf(v1, 0.f); }
                if (RESID) {
                    float2 o = *(const float2*)&C[rowoff + cg];
                    v0 += o.x; v1 += o.y;
                }
                if (OUT == 0) {
                    *(float2*)&C[rowoff + cg] = make_float2(v0, v1);
                } else if (OUT == 1) {
                    *(uint32_t*)&Cf[rowoff + cg] = packh(v0, v1);
                } else {
                    float s = (cg >= Dd) ? KVSCALE : 1.0f;
                    float y0 = v0 * s, y1 = v1 * s;
                    __half h0 = __float2half(y0), h1 = __float2half(y1);
                    union { __half h[2]; uint32_t u; } ph, pl;
                    ph.h[0] = h0; ph.h[1] = h1;
                    pl.h[0] = __float2half(y0 - __half2float(h0));
                    pl.h[1] = __float2half(y1 - __half2float(h1));
                    *(uint32_t*)&Chi[rowoff + cg] = ph.u;
                    *(uint32_t*)&Clo[rowoff + cg] = pl.u;
                }
            }
        }
    }
}

// ================= HMMA flash attention (fp16 2-pass K/V, Q frags hoisted) =================
#define APB 144
#define SM_Q  0
#define SM_KV 18432
#define KVBUF 36864
#define KVT   9216
#define ATTN_SMEM (18432 + 2 * KVBUF)

__global__ void __launch_bounds__(256, 2)
attn_mma(const __half* __restrict__ qkvhi, const __half* __restrict__ qkvlo,
         const float* __restrict__ amask, __half* __restrict__ ctx) {
    extern __shared__ char sm[];
    uint32_t sb = smem_u32(sm);
    int tid = threadIdx.x, wid = tid >> 5, lane = tid & 31;
    int i0 = blockIdx.x * 128;
    int b = blockIdx.y >> 4, h = blockIdx.y & 15;
    const size_t hq = (size_t)b * Tt * 3 * Dd + h * HD;

#pragma unroll
    for (int j = 0; j < 4; j++) {
        int lin = j * 256 + tid;
        int r = lin >> 3, seg = lin & 7;
        cpa16(sb + SM_Q + r * APB + seg * 16, qkvhi + hq + (size_t)(i0 + r) * 3 * Dd + seg * 8);
    }
    asm volatile("cp.async.commit_group;" ::: "memory");

    int ntiles = i0 / 64 + 2;

    auto issueKV = [&](int jt) {
        int j0 = jt * 64;
        uint32_t buf = sb + SM_KV + (jt & 1) * KVBUF;
#pragma unroll
        for (int j = 0; j < 8; j++) {
            int lin = j * 256 + tid;
            int t = lin >> 9;
            int l = lin & 511;
            int r = l >> 3, seg = l & 7;
            const __half* basep = (t & 1) ? qkvlo : qkvhi;
            int off = (t < 2) ? Dd : 2 * Dd;
            cpa16(buf + t * KVT + r * APB + seg * 16,
                  basep + hq + (size_t)(j0 + r) * 3 * Dd + off + seg * 8);
        }
        asm volatile("cp.async.commit_group;" ::: "memory");
    };

    issueKV(0);

    float o[8][4];
#pragma unroll
    for (int i = 0; i < 8; i++)
#pragma unroll
        for (int q = 0; q < 4; q++) o[i][q] = 0.f;
    float m_run[2] = {-1e30f, -1e30f}, l_run[2] = {0.f, 0.f};

    int r0 = lane >> 2;
    int cq = (lane & 3) * 2;
    int qrow0 = i0 + wid * 16 + r0;
    const float* amrow = amask + b * Tt;
    const float sscale = 0.125f * KVISCALE;

    uint32_t qa_off = (wid * 16 + (lane & 15)) * APB + ((lane >> 4) << 4);
    uint32_t kb_off = ((lane & 7) + ((lane >> 4) << 3)) * APB + (((lane >> 3) & 1) << 4);
    uint32_t vt_off = (lane & 15) * APB + ((lane >> 4) << 4);

    uint32_t qa[4][4];   // Q fragments, loaded once at tile 0

    for (int jt = 0; jt < ntiles; jt++) {
        int j0 = jt * 64;
        bool diag = (j0 + 63 > i0);
        asm volatile("cp.async.wait_group 0;" ::: "memory");
        __syncthreads();
        if (jt + 1 < ntiles) issueKV(jt + 1);
        if (jt == 0) {
#pragma unroll
            for (int s = 0; s < 4; s++)
                ldsm4(qa[s], sb + SM_Q + qa_off + s * 32);
        }

        uint32_t buf = sb + SM_KV + (jt & 1) * KVBUF;
        uint32_t khi_b = buf, klo_b = buf + KVT;
        uint32_t vhi_b = buf + 2 * KVT, vlo_b = buf + 3 * KVT;

        float sf[8][4];
#pragma unroll
        for (int i = 0; i < 8; i++)
#pragma unroll
            for (int q = 0; q < 4; q++) sf[i][q] = 0.f;
#pragma unroll
        for (int pass = 0; pass < 2; pass++) {
            uint32_t kb = (pass ? klo_b : khi_b);
#pragma unroll
            for (int s = 0; s < 4; s++) {
#pragma unroll
                for (int p2 = 0; p2 < 4; p2++) {
                    uint32_t bbq[4];
                    ldsm4(bbq, kb + kb_off + p2 * (16 * APB) + s * 32);
                    mma_f16(sf[p2 * 2], qa[s], bbq[0], bbq[1]);
                    mma_f16(sf[p2 * 2 + 1], qa[s], bbq[2], bbq[3]);
                }
            }
        }

#pragma unroll
        for (int nt = 0; nt < 8; nt++) {
#pragma unroll
            for (int q = 0; q < 4; q++) {
                int col = nt * 8 + cq + (q & 1);
                float am = (1.0f - __ldg(amrow + j0 + col)) * MASK_BIAS;
                float val = sf[nt][q] * sscale;
                if (diag && (j0 + col) > (qrow0 + (q >> 1) * 8)) val = MASK_BIAS;
                sf[nt][q] = val + am;
            }
        }

        float alpha[2];
#pragma unroll
        for (int rh = 0; rh < 2; rh++) {
            float mt = -1e30f;
#pragma unroll
            for (int nt = 0; nt < 8; nt++)
                mt = fmaxf(mt, fmaxf(sf[nt][rh * 2], sf[nt][rh * 2 + 1]));
            mt = fmaxf(mt, __shfl_xor_sync(0xffffffffu, mt, 1));
            mt = fmaxf(mt, __shfl_xor_sync(0xffffffffu, mt, 2));
            float mnew = fmaxf(m_run[rh], mt);
            alpha[rh] = __expf(m_run[rh] - mnew);
            m_run[rh] = mnew;
            float ls = 0.f;
#pragma unroll
            for (int nt = 0; nt < 8; nt++) {
                sf[nt][rh * 2] = __expf(sf[nt][rh * 2] - mnew);
                sf[nt][rh * 2 + 1] = __expf(sf[nt][rh * 2 + 1] - mnew);
                ls += sf[nt][rh * 2] + sf[nt][rh * 2 + 1];
            }
            ls += __shfl_xor_sync(0xffffffffu, ls, 1);
            ls += __shfl_xor_sync(0xffffffffu, ls, 2);
            l_run[rh] = l_run[rh] * alpha[rh] + ls;
        }
#pragma unroll
        for (int nt = 0; nt < 8; nt++) {
            o[nt][0] *= alpha[0]; o[nt][1] *= alpha[0];
            o[nt][2] *= alpha[1]; o[nt][3] *= alpha[1];
        }

#pragma unroll
        for (int s2 = 0; s2 < 4; s2++) {
            uint32_t ph[4];
            ph[0] = packh(sf[2 * s2][0], sf[2 * s2][1]);
            ph[1] = packh(sf[2 * s2][2], sf[2 * s2][3]);
            ph[2] = packh(sf[2 * s2 + 1][0], sf[2 * s2 + 1][1]);
            ph[3] = packh(sf[2 * s2 + 1][2], sf[2 * s2 + 1][3]);
#pragma unroll
            for (int p2 = 0; p2 < 4; p2++) {
                uint32_t vaddr = s2 * (16 * APB) + vt_off + p2 * 32;
                uint32_t bh[4], bl[4];
                ldsm4t(bh, vhi_b + vaddr);
                ldsm4t(bl, vlo_b + vaddr);
                mma_f16(o[p2 * 2], ph, bh[0], bh[1]);
                mma_f16(o[p2 * 2 + 1], ph, bh[2], bh[3]);
                mma_f16(o[p2 * 2], ph, bl[0], bl[1]);
                mma_f16(o[p2 * 2 + 1], ph, bl[2], bl[3]);
            }
        }
    }

    float inv[2] = {KVISCALE / l_run[0], KVISCALE / l_run[1]};
#pragma unroll
    for (int nt = 0; nt < 8; nt++) {
        int d0 = nt * 8 + cq;
#pragma unroll
        for (int rh = 0; rh < 2; rh++) {
            int row = i0 + wid * 16 + r0 + rh * 8;
            size_t off = (size_t)(b * Tt + row) * Dd + h * HD + d0;
            *(uint32_t*)&ctx[off] = packh(o[nt][rh * 2] * inv[rh], o[nt][rh * 2 + 1] * inv[rh]);
        }
    }
}

// ================= host launcher =================
extern "C" void kernel_launch(void* const* d_in, const int* in_sizes, int n_in,
                              void* d_out, int out_size) {
    const float* inputs_embeds = (const float*)d_in[0];
    const float* attention_mask = (const float*)d_in[1];
    const float* ln1_w = (const float*)d_in[2];
    const float* ln1_b = (const float*)d_in[3];
    const float* attn_w = (const float*)d_in[4];
    const float* attn_b = (const float*)d_in[5];
    const float* proj_w = (const float*)d_in[6];
    const float* proj_b = (const float*)d_in[7];
    const float* ln2_w = (const float*)d_in[8];
    const float* ln2_b = (const float*)d_in[9];
    const float* fc_w = (const float*)d_in[10];
    const float* fc_b = (const float*)d_in[11];
    const float* fcp_w = (const float*)d_in[12];
    const float* fcp_b = (const float*)d_in[13];
    const float* lnf_w = (const float*)d_in[14];
    const float* lnf_b = (const float*)d_in[15];
    float* out = (float*)d_out;

    cudaFuncSetAttribute(attn_mma, cudaFuncAttributeMaxDynamicSharedMemorySize, ATTN_SMEM);
    cudaFuncSetAttribute(gemm_mma<false, false, 2>, cudaFuncAttributeMaxDynamicSharedMemorySize, GEMM_SMEM);
    cudaFuncSetAttribute(gemm_mma<false, true, 0>, cudaFuncAttributeMaxDynamicSharedMemorySize, GEMM_SMEM);
    cudaFuncSetAttribute(gemm_mma<true, false, 1>, cudaFuncAttributeMaxDynamicSharedMemorySize, GEMM_SMEM);

    float *ph;
    __half *pqh, *pql, *px16, *pctx, *pff;
    __half *wq, *wp, *wf, *wg;
    cudaGetSymbolAddress((void**)&ph, g_h);
    cudaGetSymbolAddress((void**)&pqh, g_qkvhi);
    cudaGetSymbolAddress((void**)&pql, g_qkvlo);
    cudaGetSymbolAddress((void**)&px16, g_x16);
    cudaGetSymbolAddress((void**)&pctx, g_ctx16);
    cudaGetSymbolAddress((void**)&pff, g_ff16);
    cudaGetSymbolAddress((void**)&wq, g_wqkv);
    cudaGetSymbolAddress((void**)&wp, g_wproj);
    cudaGetSymbolAddress((void**)&wf, g_wfc);
    cudaGetSymbolAddress((void**)&wg, g_wfcp);

    const int MT = Bb * Tt;

    copy_kernel<<<(MT * Dd / 4) / 256, 256>>>(inputs_embeds);

    // weight conversion, batched over layers via blockIdx.z (4 launches total)
    wconv_kernel<<<dim3(3 * Dd / 64, Dd / 64, Ll), 256>>>(attn_w, wq, Dd, 3 * Dd);
    wconv_kernel<<<dim3(Dd / 64, Dd / 64, Ll), 256>>>(proj_w, wp, Dd, Dd);
    wconv_kernel<<<dim3(II / 64, Dd / 64, Ll), 256>>>(fc_w, wf, Dd, II);
    wconv_kernel<<<dim3(Dd / 64, II / 64, Ll), 256>>>(fcp_w, wg, II, Dd);

    for (int l = 0; l < Ll; l++) {
        ln_kernel<true><<<MT, 256>>>(ph, ln1_w + (size_t)l * Dd, ln1_b + (size_t)l * Dd, nullptr, px16);
        gemm_mma<false, false, 2><<<dim3(3 * Dd / 128, MT / 128), 128, GEMM_SMEM>>>(
            px16, wq + (size_t)l * 3 * Dd * Dd,
            attn_b + (size_t)l * 3 * Dd, nullptr, nullptr, pqh, pql, MT, 3 * Dd, Dd);
        attn_mma<<<dim3(Tt / 128, Bb * Hh), 256, ATTN_SMEM>>>(pqh, pql, attention_mask, pctx);
        gemm_mma<false, true, 0><<<dim3(Dd / 128, MT / 128), 128, GEMM_SMEM>>>(
            pctx, wp + (size_t)l * Dd * Dd,
            proj_b + (size_t)l * Dd, ph, nullptr, nullptr, nullptr, MT, Dd, Dd);
        ln_kernel<true><<<MT, 256>>>(ph, ln2_w + (size_t)l * Dd, ln2_b + (size_t)l * Dd, nullptr, px16);
        gemm_mma<true, false, 1><<<dim3(II / 128, MT / 128), 128, GEMM_SMEM>>>(
            px16, wf + (size_t)l * II * Dd,
            fc_b + (size_t)l * II, nullptr, pff, nullptr, nullptr, MT, II, Dd);
        gemm_mma<false, true, 0><<<dim3(Dd / 128, MT / 128), 128, GEMM_SMEM>>>(
            pff, wg + (size_t)l * Dd * II,
            fcp_b + (size_t)l * Dd, ph, nullptr, nullptr, nullptr, MT, Dd, II);
    }
    ln_kernel<false><<<MT, 256>>>(ph, lnf_w, lnf_b, out, nullptr);
}